// round 8
// baseline (speedup 1.0000x reference)
#include <cuda_runtime.h>
#include <cuda_fp16.h>
#include <cstdint>

// GRU (SEQ=1, h0=0 => w_hh unused) via warp-level HMMA m16n8k16 fragment
// chaining. Round 8: 4 M-tiles in flight per warp with the tile loop INSIDE
// each (layer, unit-group) so B fragments/biases are loaded once and reused
// 4x (L1 LDSM traffic /4) and the 4 tiles form independent ILP chains.

#define TPB     256
#define LAYERS  5
#define WSTRIDE 40    // halves per W row (80 B): conflict-free LDS/LDSM
#define NT      4     // M-tiles (16 rows) in flight per warp

struct __align__(16) Smem {
    __half  W[LAYERS * 96 * WSTRIDE];  // rows 0-63 (r,z) pre-scaled by 0.5
    __half  FCW[32 * WSTRIDE];
    float   BRZ[LAYERS * 64];          // 0.5*(b_ih+b_hh): r units 0..31, z 32..63
    float   BNI[LAYERS * 32];          // b_ih (n gate)
    __half2 BNH2[LAYERS * 16];         // b_hh (n gate) packed pairs
    float   FCB[32];
};

__device__ __forceinline__ uint32_t pack_h2(float lo, float hi) {
    uint32_t r;  // first src -> upper 16 bits
    asm("cvt.rn.f16x2.f32 %0, %1, %2;" : "=r"(r) : "f"(hi), "f"(lo));
    return r;
}
__device__ __forceinline__ uint32_t tanh2(uint32_t x) {
    uint32_t y; asm("tanh.approx.f16x2 %0, %1;" : "=r"(y) : "r"(x)); return y;
}
__device__ __forceinline__ uint32_t hfma2(uint32_t a, uint32_t b, uint32_t c) {
    uint32_t d; asm("fma.rn.f16x2 %0, %1, %2, %3;" : "=r"(d) : "r"(a), "r"(b), "r"(c));
    return d;
}
__device__ __forceinline__ uint32_t hmul2(uint32_t a, uint32_t b) {
    uint32_t d; asm("mul.rn.f16x2 %0, %1, %2;" : "=r"(d) : "r"(a), "r"(b));
    return d;
}
__device__ __forceinline__ void mma_acc(float* d, const uint32_t* a, const uint32_t* b) {
    asm volatile(
        "mma.sync.aligned.m16n8k16.row.col.f32.f16.f16.f32 "
        "{%0,%1,%2,%3}, {%4,%5,%6,%7}, {%8,%9}, {%0,%1,%2,%3};"
        : "+f"(d[0]), "+f"(d[1]), "+f"(d[2]), "+f"(d[3])
        : "r"(a[0]), "r"(a[1]), "r"(a[2]), "r"(a[3]), "r"(b[0]), "r"(b[1]));
}
__device__ __forceinline__ void mma_bias(float* d, const uint32_t* a, const uint32_t* b,
                                         float cx, float cy) {
    asm volatile(
        "mma.sync.aligned.m16n8k16.row.col.f32.f16.f16.f32 "
        "{%0,%1,%2,%3}, {%4,%5,%6,%7}, {%8,%9}, {%10,%11,%10,%11};"
        : "=f"(d[0]), "=f"(d[1]), "=f"(d[2]), "=f"(d[3])
        : "r"(a[0]), "r"(a[1]), "r"(a[2]), "r"(a[3]), "r"(b[0]), "r"(b[1]),
          "f"(cx), "f"(cy));
}
__device__ __forceinline__ void ldsm_x4(uint32_t* r, uint32_t saddr) {
    asm volatile("ldmatrix.sync.aligned.m8n8.x4.shared.b16 {%0,%1,%2,%3}, [%4];"
        : "=r"(r[0]), "=r"(r[1]), "=r"(r[2]), "=r"(r[3]) : "r"(saddr));
}

__global__ void __launch_bounds__(TPB, 2)
gru_hmma_kernel(const float* __restrict__ x,
                const float* __restrict__ w_ih,
                const float* __restrict__ b_ih,
                const float* __restrict__ b_hh,
                const float* __restrict__ fc_w,
                const float* __restrict__ fc_b,
                float* __restrict__ out)
{
    __shared__ Smem S;
    const int tid = threadIdx.x;

    // ---- stage weights (r/z rows scaled 0.5) + fused biases ----
    for (int i = tid; i < LAYERS * 96 * 32; i += TPB) {
        int l = i / 3072, row = (i % 3072) >> 5, k = i & 31;
        float scale = (row < 64) ? 0.5f : 1.0f;
        S.W[(l * 96 + row) * WSTRIDE + k] = __float2half(w_ih[i] * scale);
    }
    for (int i = tid; i < 32 * 32; i += TPB)
        S.FCW[(i >> 5) * WSTRIDE + (i & 31)] = __float2half(fc_w[i]);
    for (int i = tid; i < LAYERS * 96; i += TPB) {
        int l = i / 96, r = i % 96;
        if (r < 64) S.BRZ[l * 64 + r] = 0.5f * (b_ih[i] + b_hh[i]);
        else        S.BNI[l * 32 + r - 64] = b_ih[i];
    }
    for (int i = tid; i < LAYERS * 16; i += TPB) {
        int l = i / 16, p = i % 16;
        S.BNH2[i] = __floats2half2_rn(b_hh[l * 96 + 64 + 2 * p],
                                      b_hh[l * 96 + 64 + 2 * p + 1]);
    }
    for (int i = tid; i < 32; i += TPB) S.FCB[i] = fc_b[i];
    __syncthreads();

    const int warp = tid >> 5, lane = tid & 31;
    const int qrow = lane >> 2;
    const int c    = (lane & 3) * 2;

    const uint32_t H05  = 0x38003800u;   // half2(+0.5)
    const uint32_t HN05 = 0xB800B800u;   // half2(-0.5)

    const uint32_t lm_off = (uint32_t)((lane & 7) * (WSTRIDE * 2)
                                       + ((lane >> 4) & 1) * 32
                                       + ((lane >> 3) & 1) * 16);
    const uint32_t wbase = (uint32_t)__cvta_generic_to_shared(S.W)   + lm_off;
    const uint32_t fbase = (uint32_t)__cvta_generic_to_shared(S.FCW) + lm_off;

    // warp covers 64 rows = 4 tiles of 16
    const size_t r0 = (size_t)blockIdx.x * (64 * (TPB / 32)) + warp * 64 + qrow;

    // ---- A fragments for 4 tiles, layer 1, from gmem (fp32 -> f16x2) ----
    uint32_t A[NT][2][4];
#pragma unroll
    for (int t = 0; t < NT; t++) {
        const size_t rt = r0 + t * 16;
#pragma unroll
        for (int q = 0; q < 2; q++) {
            const float* p0 = x + rt * 32 + q * 16 + c;
            const float* p1 = x + (rt + 8) * 32 + q * 16 + c;
            float2 v00 = *(const float2*)p0;
            float2 v10 = *(const float2*)p1;
            float2 v01 = *(const float2*)(p0 + 8);
            float2 v11 = *(const float2*)(p1 + 8);
            A[t][q][0] = pack_h2(v00.x, v00.y);
            A[t][q][1] = pack_h2(v10.x, v10.y);
            A[t][q][2] = pack_h2(v01.x, v01.y);
            A[t][q][3] = pack_h2(v11.x, v11.y);
        }
    }

    // ---- 5 GRU layers: B loaded once per (l, j), reused over 4 tiles ----
#pragma unroll
    for (int l = 0; l < LAYERS; l++) {
        uint32_t nA[NT][2][4];
#pragma unroll
        for (int j = 0; j < 4; j++) {
            uint32_t Br[4], Bz[4], Bn[4];
            const uint32_t la = wbase + (uint32_t)((l * 96 + j * 8) * (WSTRIDE * 2));
            ldsm_x4(Br, la);
            ldsm_x4(Bz, la + 32 * (WSTRIDE * 2));
            ldsm_x4(Bn, la + 64 * (WSTRIDE * 2));

            const float2 br = *(const float2*)&S.BRZ[l * 64      + j * 8 + c];
            const float2 bz = *(const float2*)&S.BRZ[l * 64 + 32 + j * 8 + c];
            const float2 bi = *(const float2*)&S.BNI[l * 32      + j * 8 + c];
            const uint32_t bh2 = *(const uint32_t*)&S.BNH2[l * 16 + j * 4 + (lane & 3)];

#pragma unroll
            for (int t = 0; t < NT; t++) {       // 4 independent chains
                float Dr[4], Dz[4], Dn[4];
                mma_bias(Dr, A[t][0], Br + 0, br.x, br.y); mma_acc(Dr, A[t][1], Br + 2);
                mma_bias(Dz, A[t][0], Bz + 0, bz.x, bz.y); mma_acc(Dz, A[t][1], Bz + 2);
                mma_bias(Dn, A[t][0], Bn + 0, bi.x, bi.y); mma_acc(Dn, A[t][1], Bn + 2);
#pragma unroll
                for (int p = 0; p < 2; p++) {
                    uint32_t dr2 = pack_h2(Dr[2*p], Dr[2*p+1]);
                    uint32_t dz2 = pack_h2(Dz[2*p], Dz[2*p+1]);
                    uint32_t dn2 = pack_h2(Dn[2*p], Dn[2*p+1]);
                    uint32_t rr2 = hfma2(tanh2(dr2), H05, H05);     // sigmoid
                    uint32_t zc2 = hfma2(tanh2(dz2), HN05, H05);    // 1 - z
                    uint32_t n2  = tanh2(hfma2(rr2, bh2, dn2));
                    nA[t][j >> 1][(j & 1) * 2 + p] = hmul2(zc2, n2); // (1-z)*n
                }
            }
        }
#pragma unroll
        for (int t = 0; t < NT; t++)
#pragma unroll
            for (int q = 0; q < 2; q++)
#pragma unroll
                for (int e = 0; e < 4; e++) A[t][q][e] = nA[t][q][e];
    }

    // ---- FC: Bf loaded once per jt, reused over 4 tiles ----
#pragma unroll
    for (int jt = 0; jt < 4; jt++) {
        uint32_t Bf[4];
        ldsm_x4(Bf, fbase + (uint32_t)(jt * 8 * (WSTRIDE * 2)));
        const float2 fb = *(const float2*)&S.FCB[jt * 8 + c];
#pragma unroll
        for (int t = 0; t < NT; t++) {
            float D[4];
            mma_bias(D, A[t][0], Bf + 0, fb.x, fb.y);
            mma_acc(D, A[t][1], Bf + 2);
            const size_t rt = r0 + t * 16;
            *(float2*)&out[rt * 32       + jt * 8 + c] = make_float2(D[0], D[1]);
            *(float2*)&out[(rt + 8) * 32 + jt * 8 + c] = make_float2(D[2], D[3]);
        }
    }
}

extern "C" void kernel_launch(void* const* d_in, const int* in_sizes, int n_in,
                              void* d_out, int out_size)
{
    const float* x    = (const float*)d_in[0];
    const float* w_ih = (const float*)d_in[1];
    // d_in[2] = w_hh : unused (SEQ=1, h0=0)
    const float* b_ih = (const float*)d_in[3];
    const float* b_hh = (const float*)d_in[4];
    const float* fc_w = (const float*)d_in[5];
    const float* fc_b = (const float*)d_in[6];
    float* out = (float*)d_out;

    const int batch = in_sizes[0] / 32;          // 1048576
    const int grid  = batch / (64 * (TPB / 32)); // 2048

    gru_hmma_kernel<<<grid, TPB>>>(x, w_ih, b_ih, b_hh, fc_w, fc_b, out);
}

// round 9
// speedup vs baseline: 1.0726x; 1.0726x over previous
#include <cuda_runtime.h>
#include <cuda_fp16.h>
#include <cstdint>

// GRU (SEQ=1, h0=0 => w_hh unused) via warp-level HMMA m16n8k16 fragment
// chaining. Round 9: R7 structure (1 tile/warp, max warps) + fp16-accumulator
// gate MMAs: f16 D-fragment == tanh.approx.f16x2 input (no pack cvts), bias
// via f16 C operand, D regs halved -> <=64 regs -> 4 CTAs/SM (32 warps).
// FC MMA keeps f32 accumulation.

#define TPB     256
#define LAYERS  5
#define WSTRIDE 40    // halves per W row (80 B): conflict-free LDS/LDSM
#define NTILES  2     // 128-row halves per CTA

struct __align__(16) Smem {
    __half  W[LAYERS * 96 * WSTRIDE];  // rows 0-63 (r,z) pre-scaled by 0.5
    __half  FCW[32 * WSTRIDE];
    __half2 BG2[LAYERS * 48];          // [0..15] r fused*0.5, [16..31] z fused*0.5,
                                       // [32..47] n-gate b_ih (unit pairs)
    __half2 BNH2[LAYERS * 16];         // n-gate b_hh (unit pairs)
    float   FCB[32];
};

__device__ __forceinline__ uint32_t pack_h2(float lo, float hi) {
    uint32_t r;  // first src -> upper 16 bits
    asm("cvt.rn.f16x2.f32 %0, %1, %2;" : "=r"(r) : "f"(hi), "f"(lo));
    return r;
}
__device__ __forceinline__ uint32_t tanh2(uint32_t x) {
    uint32_t y; asm("tanh.approx.f16x2 %0, %1;" : "=r"(y) : "r"(x)); return y;
}
__device__ __forceinline__ uint32_t hfma2(uint32_t a, uint32_t b, uint32_t c) {
    uint32_t d; asm("fma.rn.f16x2 %0, %1, %2, %3;" : "=r"(d) : "r"(a), "r"(b), "r"(c));
    return d;
}
__device__ __forceinline__ uint32_t hmul2(uint32_t a, uint32_t b) {
    uint32_t d; asm("mul.rn.f16x2 %0, %1, %2;" : "=r"(d) : "r"(a), "r"(b));
    return d;
}
// f16-accumulator MMA, fresh D = A*B + {c2,c2} (bias rides the C operand)
__device__ __forceinline__ void mma_h_bias(uint32_t* d, const uint32_t* a,
                                           const uint32_t* b, uint32_t c2) {
    asm volatile(
        "mma.sync.aligned.m16n8k16.row.col.f16.f16.f16.f16 "
        "{%0,%1}, {%2,%3,%4,%5}, {%6,%7}, {%8,%8};"
        : "=r"(d[0]), "=r"(d[1])
        : "r"(a[0]), "r"(a[1]), "r"(a[2]), "r"(a[3]), "r"(b[0]), "r"(b[1]), "r"(c2));
}
// f16-accumulator MMA, D += A*B
__device__ __forceinline__ void mma_h_acc(uint32_t* d, const uint32_t* a,
                                          const uint32_t* b) {
    asm volatile(
        "mma.sync.aligned.m16n8k16.row.col.f16.f16.f16.f16 "
        "{%0,%1}, {%2,%3,%4,%5}, {%6,%7}, {%0,%1};"
        : "+r"(d[0]), "+r"(d[1])
        : "r"(a[0]), "r"(a[1]), "r"(a[2]), "r"(a[3]), "r"(b[0]), "r"(b[1]));
}
// f32-accumulator MMAs for the FC epilogue
__device__ __forceinline__ void mma_f_bias(float* d, const uint32_t* a, const uint32_t* b,
                                           float cx, float cy) {
    asm volatile(
        "mma.sync.aligned.m16n8k16.row.col.f32.f16.f16.f32 "
        "{%0,%1,%2,%3}, {%4,%5,%6,%7}, {%8,%9}, {%10,%11,%10,%11};"
        : "=f"(d[0]), "=f"(d[1]), "=f"(d[2]), "=f"(d[3])
        : "r"(a[0]), "r"(a[1]), "r"(a[2]), "r"(a[3]), "r"(b[0]), "r"(b[1]),
          "f"(cx), "f"(cy));
}
__device__ __forceinline__ void mma_f_acc(float* d, const uint32_t* a, const uint32_t* b) {
    asm volatile(
        "mma.sync.aligned.m16n8k16.row.col.f32.f16.f16.f32 "
        "{%0,%1,%2,%3}, {%4,%5,%6,%7}, {%8,%9}, {%0,%1,%2,%3};"
        : "+f"(d[0]), "+f"(d[1]), "+f"(d[2]), "+f"(d[3])
        : "r"(a[0]), "r"(a[1]), "r"(a[2]), "r"(a[3]), "r"(b[0]), "r"(b[1]));
}
__device__ __forceinline__ void ldsm_x4(uint32_t* r, uint32_t saddr) {
    asm volatile("ldmatrix.sync.aligned.m8n8.x4.shared.b16 {%0,%1,%2,%3}, [%4];"
        : "=r"(r[0]), "=r"(r[1]), "=r"(r[2]), "=r"(r[3]) : "r"(saddr));
}

__global__ void __launch_bounds__(TPB, 4)
gru_hmma_kernel(const float* __restrict__ x,
                const float* __restrict__ w_ih,
                const float* __restrict__ b_ih,
                const float* __restrict__ b_hh,
                const float* __restrict__ fc_w,
                const float* __restrict__ fc_b,
                float* __restrict__ out)
{
    __shared__ Smem S;
    const int tid = threadIdx.x;

    // ---- stage weights (r/z rows scaled 0.5) + packed biases ----
    for (int i = tid; i < LAYERS * 96 * 32; i += TPB) {
        int l = i / 3072, row = (i % 3072) >> 5, k = i & 31;
        float scale = (row < 64) ? 0.5f : 1.0f;
        S.W[(l * 96 + row) * WSTRIDE + k] = __float2half(w_ih[i] * scale);
    }
    for (int i = tid; i < 32 * 32; i += TPB)
        S.FCW[(i >> 5) * WSTRIDE + (i & 31)] = __float2half(fc_w[i]);
    for (int i = tid; i < LAYERS * 48; i += TPB) {
        int l = i / 48, p = i % 48;
        float v0, v1;
        if (p < 16) {            // r gate, units 2p, 2p+1 (rows 0..31)
            int u = l * 96 + 2 * p;
            v0 = 0.5f * (b_ih[u] + b_hh[u]);
            v1 = 0.5f * (b_ih[u + 1] + b_hh[u + 1]);
        } else if (p < 32) {     // z gate, rows 32..63
            int u = l * 96 + 32 + 2 * (p - 16);
            v0 = 0.5f * (b_ih[u] + b_hh[u]);
            v1 = 0.5f * (b_ih[u + 1] + b_hh[u + 1]);
        } else {                 // n gate b_ih, rows 64..95
            int u = l * 96 + 64 + 2 * (p - 32);
            v0 = b_ih[u];
            v1 = b_ih[u + 1];
        }
        S.BG2[i] = __floats2half2_rn(v0, v1);
    }
    for (int i = tid; i < LAYERS * 16; i += TPB) {
        int l = i / 16, p = i % 16;
        S.BNH2[i] = __floats2half2_rn(b_hh[l * 96 + 64 + 2 * p],
                                      b_hh[l * 96 + 64 + 2 * p + 1]);
    }
    for (int i = tid; i < 32; i += TPB) S.FCB[i] = fc_b[i];
    __syncthreads();

    const int warp = tid >> 5, lane = tid & 31;
    const int qrow = lane >> 2;
    const int c    = (lane & 3) * 2;
    const int cp   = lane & 3;            // unit-pair index within j-group

    const uint32_t H05  = 0x38003800u;    // half2(+0.5)
    const uint32_t HN05 = 0xB800B800u;    // half2(-0.5)

    const uint32_t lm_off = (uint32_t)((lane & 7) * (WSTRIDE * 2)
                                       + ((lane >> 4) & 1) * 32
                                       + ((lane >> 3) & 1) * 16);
    const uint32_t wbase = (uint32_t)__cvta_generic_to_shared(S.W)   + lm_off;
    const uint32_t fbase = (uint32_t)__cvta_generic_to_shared(S.FCW) + lm_off;

#pragma unroll 1
    for (int it = 0; it < NTILES; it++) {
        const size_t r0 = (size_t)blockIdx.x * (128 * NTILES) + it * 128
                          + warp * 16 + qrow;

        // ---- A fragments for layer 1 from gmem (fp32 -> f16x2) ----
        uint32_t A[2][4];
#pragma unroll
        for (int q = 0; q < 2; q++) {
            const float* p0 = x + r0 * 32 + q * 16 + c;
            const float* p1 = x + (r0 + 8) * 32 + q * 16 + c;
            float2 v00 = *(const float2*)p0;
            float2 v10 = *(const float2*)p1;
            float2 v01 = *(const float2*)(p0 + 8);
            float2 v11 = *(const float2*)(p1 + 8);
            A[q][0] = pack_h2(v00.x, v00.y);
            A[q][1] = pack_h2(v10.x, v10.y);
            A[q][2] = pack_h2(v01.x, v01.y);
            A[q][3] = pack_h2(v11.x, v11.y);
        }

        // ---- 5 GRU layers ----
#pragma unroll
        for (int l = 0; l < LAYERS; l++) {
            uint32_t nA[2][4];
#pragma unroll
            for (int j = 0; j < 4; j++) {
                uint32_t Br[4], Bz[4], Bn[4];
                const uint32_t la = wbase + (uint32_t)((l * 96 + j * 8) * (WSTRIDE * 2));
                ldsm_x4(Br, la);
                ldsm_x4(Bz, la + 32 * (WSTRIDE * 2));
                ldsm_x4(Bn, la + 64 * (WSTRIDE * 2));

                const uint32_t br2 = *(const uint32_t*)&S.BG2[l * 48      + j * 4 + cp];
                const uint32_t bz2 = *(const uint32_t*)&S.BG2[l * 48 + 16 + j * 4 + cp];
                const uint32_t bi2 = *(const uint32_t*)&S.BG2[l * 48 + 32 + j * 4 + cp];
                const uint32_t bh2 = *(const uint32_t*)&S.BNH2[l * 16 + j * 4 + cp];

                uint32_t Dr2[2], Dz2[2], Dn2[2];
                mma_h_bias(Dr2, A[0], Br + 0, br2); mma_h_acc(Dr2, A[1], Br + 2);
                mma_h_bias(Dz2, A[0], Bz + 0, bz2); mma_h_acc(Dz2, A[1], Bz + 2);
                mma_h_bias(Dn2, A[0], Bn + 0, bi2); mma_h_acc(Dn2, A[1], Bn + 2);
#pragma unroll
                for (int p = 0; p < 2; p++) {
                    uint32_t rr2 = hfma2(tanh2(Dr2[p]), H05, H05);    // sigmoid
                    uint32_t zc2 = hfma2(tanh2(Dz2[p]), HN05, H05);   // 1 - z
                    uint32_t n2  = tanh2(hfma2(rr2, bh2, Dn2[p]));
                    nA[j >> 1][(j & 1) * 2 + p] = hmul2(zc2, n2);     // (1-z)*n
                }
            }
#pragma unroll
            for (int q = 0; q < 2; q++)
#pragma unroll
                for (int e = 0; e < 4; e++) A[q][e] = nA[q][e];
        }

        // ---- FC: out = H @ fc_w^T + fc_b (f32 accumulation) ----
#pragma unroll
        for (int jt = 0; jt < 4; jt++) {
            uint32_t Bf[4];
            ldsm_x4(Bf, fbase + (uint32_t)(jt * 8 * (WSTRIDE * 2)));
            const float2 fb = *(const float2*)&S.FCB[jt * 8 + c];
            float D[4];
            mma_f_bias(D, A[0], Bf + 0, fb.x, fb.y);
            mma_f_acc(D, A[1], Bf + 2);
            *(float2*)&out[r0 * 32       + jt * 8 + c] = make_float2(D[0], D[1]);
            *(float2*)&out[(r0 + 8) * 32 + jt * 8 + c] = make_float2(D[2], D[3]);
        }
    }
}

extern "C" void kernel_launch(void* const* d_in, const int* in_sizes, int n_in,
                              void* d_out, int out_size)
{
    const float* x    = (const float*)d_in[0];
    const float* w_ih = (const float*)d_in[1];
    // d_in[2] = w_hh : unused (SEQ=1, h0=0)
    const float* b_ih = (const float*)d_in[3];
    const float* b_hh = (const float*)d_in[4];
    const float* fc_w = (const float*)d_in[5];
    const float* fc_b = (const float*)d_in[6];
    float* out = (float*)d_out;

    const int batch = in_sizes[0] / 32;        // 1048576
    const int grid  = batch / (128 * NTILES);  // 4096

    gru_hmma_kernel<<<grid, TPB>>>(x, w_ih, b_ih, b_hh, fc_w, fc_b, out);
}